// round 1
// baseline (speedup 1.0000x reference)
#include <cuda_runtime.h>
#include <cstdint>

#define TSTEPS 2048
#define NBATCH 64
#define ISZ 256
#define HSZ 256
#define G4SZ 1024

// 512 MB scratch for x_gates = input @ W_ih^T + b_ih + b_hh  (T,B,4H)
__device__ float g_xg[(size_t)TSTEPS * NBATCH * G4SZ];

// ---------- packed f32x2 helpers ----------
__device__ __forceinline__ unsigned long long pack2(float x, float y) {
    unsigned long long r;
    asm("mov.b64 %0, {%1, %2};" : "=l"(r) : "f"(x), "f"(y));
    return r;
}
__device__ __forceinline__ unsigned long long fma2(unsigned long long a,
                                                   unsigned long long b,
                                                   unsigned long long c) {
    unsigned long long d;
    asm("fma.rn.f32x2 %0, %1, %2, %3;" : "=l"(d) : "l"(a), "l"(b), "l"(c));
    return d;
}
__device__ __forceinline__ float2 unpack2(unsigned long long v) {
    float2 r;
    asm("mov.b64 {%0, %1}, %2;" : "=f"(r.x), "=f"(r.y) : "l"(v));
    return r;
}

__device__ __forceinline__ float sigf(float x) {
    return __fdividef(1.f, 1.f + __expf(-x));
}
__device__ __forceinline__ float tanhfastf(float x) {
    return 2.f * __fdividef(1.f, 1.f + __expf(-2.f * x)) - 1.f;
}

// ============================================================
// Kernel A: x_gates GEMM.  C[M=131072, N=1024] = A[M,256] @ W[N,256]^T + bias
// 128x64 tiles, BK=16, 256 threads, 8x4 micro-tile, packed f32x2 FMA.
// ============================================================
#define BM 128
#define BN 64
#define BK 16
#define ASTR 132
#define BSTR 68

__global__ __launch_bounds__(256) void xg_gemm(
    const float* __restrict__ A, const float* __restrict__ W,
    const float* __restrict__ b1, const float* __restrict__ b2)
{
    __shared__ float As[BK * ASTR];  // [k][m]
    __shared__ float Bs[BK * BSTR];  // [k][n]
    int tid = threadIdx.x;
    int tx = tid & 15, ty = tid >> 4;
    size_t mBase = (size_t)blockIdx.x * BM;
    int nBase = blockIdx.y * BN;

    unsigned long long z = pack2(0.f, 0.f);
    unsigned long long acc[8][2];
#pragma unroll
    for (int i = 0; i < 8; i++) { acc[i][0] = z; acc[i][1] = z; }

    for (int kt = 0; kt < ISZ; kt += BK) {
        // A tile: 128x16 floats = 512 float4, 2 per thread, store transposed
#pragma unroll
        for (int it = tid; it < (BM * BK / 4); it += 256) {
            int m = it >> 2, kq = it & 3;
            float4 v = *(const float4*)(A + (mBase + m) * ISZ + kt + kq * 4);
            As[(kq * 4 + 0) * ASTR + m] = v.x;
            As[(kq * 4 + 1) * ASTR + m] = v.y;
            As[(kq * 4 + 2) * ASTR + m] = v.z;
            As[(kq * 4 + 3) * ASTR + m] = v.w;
        }
        // B tile: 64x16 floats = 256 float4, 1 per thread
        {
            int n = tid >> 2, kq = tid & 3;
            float4 v = *(const float4*)(W + (size_t)(nBase + n) * ISZ + kt + kq * 4);
            Bs[(kq * 4 + 0) * BSTR + n] = v.x;
            Bs[(kq * 4 + 1) * BSTR + n] = v.y;
            Bs[(kq * 4 + 2) * BSTR + n] = v.z;
            Bs[(kq * 4 + 3) * BSTR + n] = v.w;
        }
        __syncthreads();
#pragma unroll
        for (int kk = 0; kk < BK; kk++) {
            float4 a0 = *(const float4*)(As + kk * ASTR + ty * 8);
            float4 a1 = *(const float4*)(As + kk * ASTR + ty * 8 + 4);
            float4 bv = *(const float4*)(Bs + kk * BSTR + tx * 4);
            unsigned long long bp0 = pack2(bv.x, bv.y);
            unsigned long long bp1 = pack2(bv.z, bv.w);
            float am[8] = {a0.x, a0.y, a0.z, a0.w, a1.x, a1.y, a1.z, a1.w};
#pragma unroll
            for (int i = 0; i < 8; i++) {
                unsigned long long ap = pack2(am[i], am[i]);
                acc[i][0] = fma2(ap, bp0, acc[i][0]);
                acc[i][1] = fma2(ap, bp1, acc[i][1]);
            }
        }
        __syncthreads();
    }
    int n0 = nBase + tx * 4;
    float bx = b1[n0 + 0] + b2[n0 + 0];
    float by = b1[n0 + 1] + b2[n0 + 1];
    float bz = b1[n0 + 2] + b2[n0 + 2];
    float bw = b1[n0 + 3] + b2[n0 + 3];
#pragma unroll
    for (int i = 0; i < 8; i++) {
        float2 p0 = unpack2(acc[i][0]);
        float2 p1 = unpack2(acc[i][1]);
        float4 o = make_float4(p0.x + bx, p0.y + by, p1.x + bz, p1.y + bw);
        *(float4*)(g_xg + (mBase + ty * 8 + i) * G4SZ + n0) = o;
    }
}

// ============================================================
// Kernel B: recurrence. 16 independent groups (4 batches each) x cluster of 8
// CTAs. Each CTA: 32 h-cols, 128 gate rows of W_hh resident in SMEM.
// ============================================================
#define WSTR 260                 // padded W row stride (floats), 16B aligned, bank-clean
#define H_OFF 33280              // 128*260
#define RED_OFF 35328            // H_OFF + 2*256*4
#define GB_OFF 35840             // RED_OFF + 128*4
#define RSMEM_BYTES ((GB_OFF + 512) * 4)   // 145408 B

#define OUT_HT ((size_t)TSTEPS * NBATCH * HSZ)
#define OUT_CT (OUT_HT + (size_t)NBATCH * HSZ)

__global__ void __cluster_dims__(8, 1, 1) __launch_bounds__(256, 1) lstm_rec(
    const float* __restrict__ h0, const float* __restrict__ c0,
    const float* __restrict__ Whh, float* __restrict__ out, int write_tail)
{
    extern __shared__ float sm[];
    float* Wsm  = sm;              // [128][WSTR]
    float* hsm  = sm + H_OFF;      // [2][256 k][4 b]
    float* red  = sm + RED_OFF;    // [128][4]
    float* gbuf = sm + GB_OFF;     // [128][4]

    int tid = threadIdx.x;
    unsigned crank;
    asm("mov.u32 %0, %%cluster_ctarank;" : "=r"(crank));
    int grp = blockIdx.x >> 3;
    int b0 = grp * 4;

    // ---- load W_hh slice into SMEM (rows: q*256 + crank*32 + co) ----
    for (int it = tid; it < 128 * 64; it += 256) {
        int lr = it >> 6, kq = it & 63;
        int gr = (lr >> 5) * 256 + (int)crank * 32 + (lr & 31);
        float4 v = *(const float4*)(Whh + (size_t)gr * HSZ + kq * 4);
        *(float4*)(Wsm + lr * WSTR + kq * 4) = v;
    }
    // ---- init h (buffer 0): hsm[k][b] (k-major, batch fastest => f32x2 pairs) ----
    for (int it = tid; it < HSZ * 4; it += 256) {
        int k = it >> 2, b = it & 3;
        hsm[k * 4 + b] = h0[(size_t)(b0 + b) * HSZ + k];
    }
    // ---- per-thread cell state (elementwise role: tid<128) ----
    int eb = tid >> 5, eco = tid & 31;
    int ecol = (int)crank * 32 + eco;
    float creg = 0.f;
    if (tid < 128) creg = c0[(size_t)(b0 + eb) * HSZ + ecol];
    __syncthreads();

    // GEMM role: 256 threads = 128 gate rows x 2 K-halves
    int hh = tid >> 7, lr = tid & 127;
    int gr = (lr >> 5) * 256 + (int)crank * 32 + (lr & 31);
    const float* wrow = Wsm + lr * WSTR + hh * 128;
    unsigned long long z = pack2(0.f, 0.f);

    for (int t = 0; t < TSTEPS; t++) {
        int cur = t & 1, nxt = cur ^ 1;

        // prefetch this step's x_gates (latency hidden under the GEMM)
        float xgv0 = 0.f, xgv1 = 0.f, xgv2 = 0.f, xgv3 = 0.f;
        if (tid < 128) {
            const float* xp = g_xg + ((size_t)t * NBATCH + b0) * G4SZ + gr;
            xgv0 = xp[0];
            xgv1 = xp[G4SZ];
            xgv2 = xp[2 * G4SZ];
            xgv3 = xp[3 * G4SZ];
        }

        // ---- recurrent GEMM: gates[gr][b] = sum_k W[gr][k]*h[b][k] ----
        const double2* hrow = (const double2*)(hsm + cur * 1024 + hh * 512);
        unsigned long long a01 = z, a23 = z;
#pragma unroll
        for (int k4 = 0; k4 < 32; k4++) {
            float4 wv = *(const float4*)(wrow + k4 * 4);
            unsigned long long wp;
            double2 hv;
            wp = pack2(wv.x, wv.x); hv = hrow[k4 * 4 + 0];
            a01 = fma2(wp, __double_as_longlong(hv.x), a01);
            a23 = fma2(wp, __double_as_longlong(hv.y), a23);
            wp = pack2(wv.y, wv.y); hv = hrow[k4 * 4 + 1];
            a01 = fma2(wp, __double_as_longlong(hv.x), a01);
            a23 = fma2(wp, __double_as_longlong(hv.y), a23);
            wp = pack2(wv.z, wv.z); hv = hrow[k4 * 4 + 2];
            a01 = fma2(wp, __double_as_longlong(hv.x), a01);
            a23 = fma2(wp, __double_as_longlong(hv.y), a23);
            wp = pack2(wv.w, wv.w); hv = hrow[k4 * 4 + 3];
            a01 = fma2(wp, __double_as_longlong(hv.x), a01);
            a23 = fma2(wp, __double_as_longlong(hv.y), a23);
        }
        // ---- combine the two K-halves ----
        if (tid >= 128) {
            *(unsigned long long*)(red + lr * 4)     = a01;
            *(unsigned long long*)(red + lr * 4 + 2) = a23;
        }
        __syncthreads();
        if (tid < 128) {
            float2 s01 = unpack2(a01), s23 = unpack2(a23);
            float2 r01 = unpack2(*(const unsigned long long*)(red + lr * 4));
            float2 r23 = unpack2(*(const unsigned long long*)(red + lr * 4 + 2));
            gbuf[lr * 4 + 0] = s01.x + r01.x + xgv0;
            gbuf[lr * 4 + 1] = s01.y + r01.y + xgv1;
            gbuf[lr * 4 + 2] = s23.x + r23.x + xgv2;
            gbuf[lr * 4 + 3] = s23.y + r23.y + xgv3;
        }
        __syncthreads();
        // ---- elementwise LSTM cell + h broadcast to cluster peers ----
        if (tid < 128) {
            float gi = gbuf[(eco)      * 4 + eb];
            float gf = gbuf[(32 + eco) * 4 + eb];
            float gg = gbuf[(64 + eco) * 4 + eb];
            float go = gbuf[(96 + eco) * 4 + eb];
            float iv = sigf(gi), fv = sigf(gf);
            float gv = tanhfastf(gg), ov = sigf(go);
            creg = fv * creg + iv * gv;
            float hn = ov * tanhfastf(creg);

            out[((size_t)t * NBATCH + b0 + eb) * HSZ + ecol] = hn;

            uint32_t laddr = (uint32_t)__cvta_generic_to_shared(
                hsm + nxt * 1024 + ecol * 4 + eb);
#pragma unroll
            for (int p = 0; p < 8; p++) {
                uint32_t ra;
                asm volatile("mapa.shared::cluster.u32 %0, %1, %2;"
                             : "=r"(ra) : "r"(laddr), "r"(p));
                asm volatile("st.shared::cluster.f32 [%0], %1;"
                             :: "r"(ra), "f"(hn) : "memory");
            }
            if (write_tail && t == TSTEPS - 1) {
                out[OUT_HT + (size_t)(b0 + eb) * HSZ + ecol] = hn;
                out[OUT_CT + (size_t)(b0 + eb) * HSZ + ecol] = creg;
            }
        }
        // one cluster barrier per step (release/acquire orders DSMEM h writes)
        asm volatile("barrier.cluster.arrive.aligned;" ::: "memory");
        asm volatile("barrier.cluster.wait.aligned;" ::: "memory");
    }
}

// ============================================================
extern "C" void kernel_launch(void* const* d_in, const int* in_sizes, int n_in,
                              void* d_out, int out_size) {
    const float* input = (const float*)d_in[0];
    const float* h0    = (const float*)d_in[1];
    const float* c0    = (const float*)d_in[2];
    const float* W_ih  = (const float*)d_in[3];
    const float* W_hh  = (const float*)d_in[4];
    const float* b_ih  = (const float*)d_in[5];
    const float* b_hh  = (const float*)d_in[6];
    float* out = (float*)d_out;

    int write_tail = (out_size >= (int)(OUT_CT + (size_t)NBATCH * HSZ)) ? 1 : 0;

    dim3 gA((TSTEPS * NBATCH) / BM, G4SZ / BN);
    xg_gemm<<<gA, 256>>>(input, W_ih, b_ih, b_hh);

    cudaFuncSetAttribute(lstm_rec, cudaFuncAttributeMaxDynamicSharedMemorySize,
                         RSMEM_BYTES);
    lstm_rec<<<128, 256, RSMEM_BYTES>>>(h0, c0, W_hh, out, write_tail);
}

// round 2
// speedup vs baseline: 1.2341x; 1.2341x over previous
#include <cuda_runtime.h>
#include <cstdint>

#define TSTEPS 2048
#define NBATCH 64
#define ISZ 256
#define HSZ 256
#define G4SZ 1024

// 512 MB scratch for x_gates = input @ W_ih^T + b_ih + b_hh  (T,B,4H)
__device__ float g_xg[(size_t)TSTEPS * NBATCH * G4SZ];

// ---------- packed f32x2 helpers ----------
__device__ __forceinline__ unsigned long long pack2(float x, float y) {
    unsigned long long r;
    asm("mov.b64 %0, {%1, %2};" : "=l"(r) : "f"(x), "f"(y));
    return r;
}
__device__ __forceinline__ unsigned long long fma2(unsigned long long a,
                                                   unsigned long long b,
                                                   unsigned long long c) {
    unsigned long long d;
    asm("fma.rn.f32x2 %0, %1, %2, %3;" : "=l"(d) : "l"(a), "l"(b), "l"(c));
    return d;
}
__device__ __forceinline__ unsigned long long add2(unsigned long long a,
                                                   unsigned long long b) {
    unsigned long long d;
    asm("add.rn.f32x2 %0, %1, %2;" : "=l"(d) : "l"(a), "l"(b));
    return d;
}
__device__ __forceinline__ float2 unpack2(unsigned long long v) {
    float2 r;
    asm("mov.b64 {%0, %1}, %2;" : "=f"(r.x), "=f"(r.y) : "l"(v));
    return r;
}

__device__ __forceinline__ float sigf(float x) {
    return __fdividef(1.f, 1.f + __expf(-x));
}
__device__ __forceinline__ float tanhfastf(float x) {
    return 2.f * __fdividef(1.f, 1.f + __expf(-2.f * x)) - 1.f;
}

// ============================================================
// Kernel A: x_gates GEMM.  C[M=131072, N=1024] = A[M,256] @ W[N,256]^T + bias
// ============================================================
#define BM 128
#define BN 64
#define BK 16
#define ASTR 132
#define BSTR 68

__global__ __launch_bounds__(256) void xg_gemm(
    const float* __restrict__ A, const float* __restrict__ W,
    const float* __restrict__ b1, const float* __restrict__ b2)
{
    __shared__ float As[BK * ASTR];  // [k][m]
    __shared__ float Bs[BK * BSTR];  // [k][n]
    int tid = threadIdx.x;
    int tx = tid & 15, ty = tid >> 4;
    size_t mBase = (size_t)blockIdx.x * BM;
    int nBase = blockIdx.y * BN;

    unsigned long long z = pack2(0.f, 0.f);
    unsigned long long acc[8][2];
#pragma unroll
    for (int i = 0; i < 8; i++) { acc[i][0] = z; acc[i][1] = z; }

    for (int kt = 0; kt < ISZ; kt += BK) {
#pragma unroll
        for (int it = tid; it < (BM * BK / 4); it += 256) {
            int m = it >> 2, kq = it & 3;
            float4 v = *(const float4*)(A + (mBase + m) * ISZ + kt + kq * 4);
            As[(kq * 4 + 0) * ASTR + m] = v.x;
            As[(kq * 4 + 1) * ASTR + m] = v.y;
            As[(kq * 4 + 2) * ASTR + m] = v.z;
            As[(kq * 4 + 3) * ASTR + m] = v.w;
        }
        {
            int n = tid >> 2, kq = tid & 3;
            float4 v = *(const float4*)(W + (size_t)(nBase + n) * ISZ + kt + kq * 4);
            Bs[(kq * 4 + 0) * BSTR + n] = v.x;
            Bs[(kq * 4 + 1) * BSTR + n] = v.y;
            Bs[(kq * 4 + 2) * BSTR + n] = v.z;
            Bs[(kq * 4 + 3) * BSTR + n] = v.w;
        }
        __syncthreads();
#pragma unroll
        for (int kk = 0; kk < BK; kk++) {
            float4 a0 = *(const float4*)(As + kk * ASTR + ty * 8);
            float4 a1 = *(const float4*)(As + kk * ASTR + ty * 8 + 4);
            float4 bv = *(const float4*)(Bs + kk * BSTR + tx * 4);
            unsigned long long bp0 = pack2(bv.x, bv.y);
            unsigned long long bp1 = pack2(bv.z, bv.w);
            float am[8] = {a0.x, a0.y, a0.z, a0.w, a1.x, a1.y, a1.z, a1.w};
#pragma unroll
            for (int i = 0; i < 8; i++) {
                unsigned long long ap = pack2(am[i], am[i]);
                acc[i][0] = fma2(ap, bp0, acc[i][0]);
                acc[i][1] = fma2(ap, bp1, acc[i][1]);
            }
        }
        __syncthreads();
    }
    int n0 = nBase + tx * 4;
    float bx = b1[n0 + 0] + b2[n0 + 0];
    float by = b1[n0 + 1] + b2[n0 + 1];
    float bz = b1[n0 + 2] + b2[n0 + 2];
    float bw = b1[n0 + 3] + b2[n0 + 3];
#pragma unroll
    for (int i = 0; i < 8; i++) {
        float2 p0 = unpack2(acc[i][0]);
        float2 p1 = unpack2(acc[i][1]);
        float4 o = make_float4(p0.x + bx, p0.y + by, p1.x + bz, p1.y + bw);
        *(float4*)(g_xg + (mBase + ty * 8 + i) * G4SZ + n0) = o;
    }
}

// ============================================================
// Kernel B: recurrence, persistent-RNN style.
// 16 groups (4 batches) x cluster of 8 CTAs. 512 threads/CTA.
// Thread (qk = tid>>7, lr = tid&127): gate-row gr, K-quarter qk.
// W_hh slice (64 floats) lives in REGISTERS for the whole kernel.
// h is the only smem operand in the inner loop (warp-uniform -> broadcast).
// ============================================================
#define OUT_HT ((size_t)TSTEPS * NBATCH * HSZ)
#define OUT_CT (OUT_HT + (size_t)NBATCH * HSZ)

__global__ void __cluster_dims__(8, 1, 1) __launch_bounds__(512, 1) lstm_rec(
    const float* __restrict__ h0, const float* __restrict__ c0,
    const float* __restrict__ Whh, float* __restrict__ out, int write_tail)
{
    __shared__ float hsm[2 * HSZ * 4];        // [buf][k][b]  8KB
    __shared__ float red[4 * 128 * 4];        // [qk][lr][b]  8KB
    __shared__ float dummy_pad[32];           // keep layouts apart

    int tid = threadIdx.x;
    unsigned crank;
    asm("mov.u32 %0, %%cluster_ctarank;" : "=r"(crank));
    int grp = blockIdx.x >> 3;
    int b0 = grp * 4;

    int qk = tid >> 7, lr = tid & 127;
    int gr = (lr >> 5) * 256 + (int)crank * 32 + (lr & 31);  // global gate row

    // ---- W_hh slice into registers (once) ----
    float w[64];
    {
        const float* wp = Whh + (size_t)gr * HSZ + qk * 64;
#pragma unroll
        for (int i = 0; i < 16; i++) {
            float4 v = *(const float4*)(wp + i * 4);
            w[i * 4 + 0] = v.x; w[i * 4 + 1] = v.y;
            w[i * 4 + 2] = v.z; w[i * 4 + 3] = v.w;
        }
    }
    // ---- init h buffer 0: hsm[k*4+b] ----
    for (int it = tid; it < HSZ * 4; it += 512) {
        hsm[it] = h0[(size_t)(b0 + (it & 3)) * HSZ + (it >> 2)];
    }
    // ---- elementwise role state (tid < 128): (batch eb, col eco) ----
    int eb = tid >> 5, eco = tid & 31;
    int ecol = (int)crank * 32 + eco;
    float creg = 0.f;
    if (tid < 128) creg = c0[(size_t)(b0 + eb) * HSZ + ecol];
    dummy_pad[0] = 0.f;
    __syncthreads();

    unsigned long long z = pack2(0.f, 0.f);

    for (int t = 0; t < TSTEPS; t++) {
        int cur = t & 1, nxt = cur ^ 1;

        // prefetch this thread's x_gates (elementwise view): xg[t][b0+eb][g*256+ecol]
        float xg0 = 0.f, xg1 = 0.f, xg2 = 0.f, xg3 = 0.f;
        if (tid < 128) {
            const float* xp = g_xg + ((size_t)t * NBATCH + b0 + eb) * G4SZ + ecol;
            xg0 = xp[0];
            xg1 = xp[256];
            xg2 = xp[512];
            xg3 = xp[768];
        }

        // ---- recurrent GEMM: partial[gr][b] over K-quarter qk ----
        const ulonglong2* hv =
            (const ulonglong2*)(hsm + cur * (HSZ * 4) + qk * 256);
        unsigned long long a01 = z, a23 = z, c01 = z, c23 = z;
#pragma unroll
        for (int k = 0; k < 64; k += 2) {
            ulonglong2 h0v = hv[k];
            unsigned long long wp0 = pack2(w[k], w[k]);
            a01 = fma2(wp0, h0v.x, a01);
            a23 = fma2(wp0, h0v.y, a23);
            ulonglong2 h1v = hv[k + 1];
            unsigned long long wp1 = pack2(w[k + 1], w[k + 1]);
            c01 = fma2(wp1, h1v.x, c01);
            c23 = fma2(wp1, h1v.y, c23);
        }
        a01 = add2(a01, c01);
        a23 = add2(a23, c23);

        // ---- all 4 K-quarters store partials; one sync ----
        {
            ulonglong2 st; st.x = a01; st.y = a23;
            *(ulonglong2*)(red + (qk * 128 + lr) * 4) = st;
        }
        __syncthreads();

        // ---- elementwise LSTM cell (tid < 128) ----
        if (tid < 128) {
            float gsum[4];
#pragma unroll
            for (int g = 0; g < 4; g++) {
                int row = g * 32 + eco;
                float s = red[(0 * 128 + row) * 4 + eb]
                        + red[(1 * 128 + row) * 4 + eb]
                        + red[(2 * 128 + row) * 4 + eb]
                        + red[(3 * 128 + row) * 4 + eb];
                gsum[g] = s;
            }
            float gi = gsum[0] + xg0;
            float gf = gsum[1] + xg1;
            float gg = gsum[2] + xg2;
            float go = gsum[3] + xg3;
            float iv = sigf(gi), fv = sigf(gf);
            float gv = tanhfastf(gg), ov = sigf(go);
            creg = fv * creg + iv * gv;
            float hn = ov * tanhfastf(creg);

            out[((size_t)t * NBATCH + b0 + eb) * HSZ + ecol] = hn;

            // broadcast h to all 8 cluster CTAs' next-buffer
            uint32_t laddr = (uint32_t)__cvta_generic_to_shared(
                hsm + nxt * (HSZ * 4) + ecol * 4 + eb);
#pragma unroll
            for (int p = 0; p < 8; p++) {
                uint32_t ra;
                asm volatile("mapa.shared::cluster.u32 %0, %1, %2;"
                             : "=r"(ra) : "r"(laddr), "r"(p));
                asm volatile("st.shared::cluster.f32 [%0], %1;"
                             :: "r"(ra), "f"(hn) : "memory");
            }
            if (write_tail && t == TSTEPS - 1) {
                out[OUT_HT + (size_t)(b0 + eb) * HSZ + ecol] = hn;
                out[OUT_CT + (size_t)(b0 + eb) * HSZ + ecol] = creg;
            }
        }
        // one cluster barrier per step (orders DSMEM h writes; also CTA barrier,
        // protecting red[] reuse next step)
        asm volatile("barrier.cluster.arrive.aligned;" ::: "memory");
        asm volatile("barrier.cluster.wait.aligned;" ::: "memory");
    }
}

// ============================================================
extern "C" void kernel_launch(void* const* d_in, const int* in_sizes, int n_in,
                              void* d_out, int out_size) {
    const float* input = (const float*)d_in[0];
    const float* h0    = (const float*)d_in[1];
    const float* c0    = (const float*)d_in[2];
    const float* W_ih  = (const float*)d_in[3];
    const float* W_hh  = (const float*)d_in[4];
    const float* b_ih  = (const float*)d_in[5];
    const float* b_hh  = (const float*)d_in[6];
    float* out = (float*)d_out;

    int write_tail = (out_size >= (int)(OUT_CT + (size_t)NBATCH * HSZ)) ? 1 : 0;

    dim3 gA((TSTEPS * NBATCH) / BM, G4SZ / BN);
    xg_gemm<<<gA, 256>>>(input, W_ih, b_ih, b_hh);

    lstm_rec<<<128, 512>>>(h0, c0, W_hh, out, write_tail);
}

// round 3
// speedup vs baseline: 1.8639x; 1.5103x over previous
#include <cuda_runtime.h>
#include <cstdint>

#define TSTEPS 2048
#define NBATCH 64
#define ISZ 256
#define HSZ 256
#define G4SZ 1024

// 512 MB scratch for x_gates = input @ W_ih^T + b_ih + b_hh  (T,B,4H)
__device__ float g_xg[(size_t)TSTEPS * NBATCH * G4SZ];

// ---------- packed f32x2 helpers ----------
__device__ __forceinline__ unsigned long long pack2(float x, float y) {
    unsigned long long r;
    asm("mov.b64 %0, {%1, %2};" : "=l"(r) : "f"(x), "f"(y));
    return r;
}
__device__ __forceinline__ unsigned long long fma2(unsigned long long a,
                                                   unsigned long long b,
                                                   unsigned long long c) {
    unsigned long long d;
    asm("fma.rn.f32x2 %0, %1, %2, %3;" : "=l"(d) : "l"(a), "l"(b), "l"(c));
    return d;
}
__device__ __forceinline__ unsigned long long add2(unsigned long long a,
                                                   unsigned long long b) {
    unsigned long long d;
    asm("add.rn.f32x2 %0, %1, %2;" : "=l"(d) : "l"(a), "l"(b));
    return d;
}
__device__ __forceinline__ float2 unpack2(unsigned long long v) {
    float2 r;
    asm("mov.b64 {%0, %1}, %2;" : "=f"(r.x), "=f"(r.y) : "l"(v));
    return r;
}

__device__ __forceinline__ float sigf(float x) {
    return __fdividef(1.f, 1.f + __expf(-x));
}
__device__ __forceinline__ float tanhfastf(float x) {
    return 2.f * __fdividef(1.f, 1.f + __expf(-2.f * x)) - 1.f;
}

// ============================================================
// Kernel A: x_gates GEMM.  C[M=131072, N=1024] = A[M,256] @ W[N,256]^T + bias
// ============================================================
#define BM 128
#define BN 64
#define BK 16
#define ASTR 132
#define BSTR 68

__global__ __launch_bounds__(256) void xg_gemm(
    const float* __restrict__ A, const float* __restrict__ W,
    const float* __restrict__ b1, const float* __restrict__ b2)
{
    __shared__ float As[BK * ASTR];  // [k][m]
    __shared__ float Bs[BK * BSTR];  // [k][n]
    int tid = threadIdx.x;
    int tx = tid & 15, ty = tid >> 4;
    size_t mBase = (size_t)blockIdx.x * BM;
    int nBase = blockIdx.y * BN;

    unsigned long long z = pack2(0.f, 0.f);
    unsigned long long acc[8][2];
#pragma unroll
    for (int i = 0; i < 8; i++) { acc[i][0] = z; acc[i][1] = z; }

    for (int kt = 0; kt < ISZ; kt += BK) {
#pragma unroll
        for (int it = tid; it < (BM * BK / 4); it += 256) {
            int m = it >> 2, kq = it & 3;
            float4 v = *(const float4*)(A + (mBase + m) * ISZ + kt + kq * 4);
            As[(kq * 4 + 0) * ASTR + m] = v.x;
            As[(kq * 4 + 1) * ASTR + m] = v.y;
            As[(kq * 4 + 2) * ASTR + m] = v.z;
            As[(kq * 4 + 3) * ASTR + m] = v.w;
        }
        {
            int n = tid >> 2, kq = tid & 3;
            float4 v = *(const float4*)(W + (size_t)(nBase + n) * ISZ + kt + kq * 4);
            Bs[(kq * 4 + 0) * BSTR + n] = v.x;
            Bs[(kq * 4 + 1) * BSTR + n] = v.y;
            Bs[(kq * 4 + 2) * BSTR + n] = v.z;
            Bs[(kq * 4 + 3) * BSTR + n] = v.w;
        }
        __syncthreads();
#pragma unroll
        for (int kk = 0; kk < BK; kk++) {
            float4 a0 = *(const float4*)(As + kk * ASTR + ty * 8);
            float4 a1 = *(const float4*)(As + kk * ASTR + ty * 8 + 4);
            float4 bv = *(const float4*)(Bs + kk * BSTR + tx * 4);
            unsigned long long bp0 = pack2(bv.x, bv.y);
            unsigned long long bp1 = pack2(bv.z, bv.w);
            float am[8] = {a0.x, a0.y, a0.z, a0.w, a1.x, a1.y, a1.z, a1.w};
#pragma unroll
            for (int i = 0; i < 8; i++) {
                unsigned long long ap = pack2(am[i], am[i]);
                acc[i][0] = fma2(ap, bp0, acc[i][0]);
                acc[i][1] = fma2(ap, bp1, acc[i][1]);
            }
        }
        __syncthreads();
    }
    int n0 = nBase + tx * 4;
    float bx = b1[n0 + 0] + b2[n0 + 0];
    float by = b1[n0 + 1] + b2[n0 + 1];
    float bz = b1[n0 + 2] + b2[n0 + 2];
    float bw = b1[n0 + 3] + b2[n0 + 3];
#pragma unroll
    for (int i = 0; i < 8; i++) {
        float2 p0 = unpack2(acc[i][0]);
        float2 p1 = unpack2(acc[i][1]);
        float4 o = make_float4(p0.x + bx, p0.y + by, p1.x + bz, p1.y + bw);
        *(float4*)(g_xg + (mBase + ty * 8 + i) * G4SZ + n0) = o;
    }
}

// ============================================================
// Kernel B: recurrence. 16 groups x cluster of 8 CTAs, 512 thr/CTA.
// W_hh in registers (64 f/thread, pre-paired for f32x2).
// h exchange: st.async.shared::cluster + tx-counting mbarrier (NO cluster
// barrier in the loop). Double-buffered h + barriers; the recurrence's data
// dependency provides buffer backpressure.
// ============================================================
#define OUT_HT ((size_t)TSTEPS * NBATCH * HSZ)
#define OUT_CT (OUT_HT + (size_t)NBATCH * HSZ)
#define HX_BYTES 4096   // 8 CTAs * 128 vals * 4B received per step

__global__ void __cluster_dims__(8, 1, 1) __launch_bounds__(512, 1) lstm_rec(
    const float* __restrict__ h0, const float* __restrict__ c0,
    const float* __restrict__ Whh, float* __restrict__ out, int write_tail)
{
    __shared__ float hsm[2 * 4 * HSZ];          // [buf][b][k]  8KB
    __shared__ float red[4 * 128 * 4];          // [qk][lr][b]  8KB
    __shared__ __align__(8) unsigned long long mbars[2];

    int tid = threadIdx.x;
    unsigned crank;
    asm("mov.u32 %0, %%cluster_ctarank;" : "=r"(crank));
    int b0 = (blockIdx.x >> 3) * 4;

    int qk = tid >> 7, lr = tid & 127;
    int gr = (lr >> 5) * 256 + (int)crank * 32 + (lr & 31);  // global gate row

    uint32_t mb0 = (uint32_t)__cvta_generic_to_shared(&mbars[0]);
    uint32_t mb1 = (uint32_t)__cvta_generic_to_shared(&mbars[1]);

    // ---- W_hh slice -> registers, pre-paired for f32x2 ----
    unsigned long long w2[32];
    {
        const float* wp = Whh + (size_t)gr * HSZ + qk * 64;
#pragma unroll
        for (int i = 0; i < 16; i++) {
            float4 v = *(const float4*)(wp + i * 4);
            w2[i * 2 + 0] = pack2(v.x, v.y);
            w2[i * 2 + 1] = pack2(v.z, v.w);
        }
    }
    // ---- init h buffer 0: hsm[b*256+k] ----
    for (int it = tid; it < 4 * HSZ; it += 512) {
        int b = it >> 8, k = it & 255;
        hsm[b * 256 + k] = h0[(size_t)(b0 + b) * HSZ + k];
    }
    // ---- elementwise state (tid<128): (batch eb, col eco) ----
    int eb = tid >> 5, eco = tid & 31;
    int ecol = (int)crank * 32 + eco;
    float creg = 0.f;
    if (tid < 128) creg = c0[(size_t)(b0 + eb) * HSZ + ecol];

    // ---- mbarrier init + arm (count=1; expect_tx supplies the arrival) ----
    if (tid == 0) {
        asm volatile("mbarrier.init.shared.b64 [%0], 1;" :: "r"(mb0) : "memory");
        asm volatile("mbarrier.init.shared.b64 [%0], 1;" :: "r"(mb1) : "memory");
    }
    __syncthreads();
    // all cluster CTAs' barriers must be live before any peer st.async
    asm volatile("barrier.cluster.arrive.aligned;" ::: "memory");
    asm volatile("barrier.cluster.wait.aligned;" ::: "memory");
    if (tid == 0) {
        asm volatile("mbarrier.arrive.expect_tx.shared.b64 _, [%0], %1;"
                     :: "r"(mb0), "r"(HX_BYTES) : "memory");
        asm volatile("mbarrier.arrive.expect_tx.shared.b64 _, [%0], %1;"
                     :: "r"(mb1), "r"(HX_BYTES) : "memory");
    }
    __syncthreads();

    unsigned long long z = pack2(0.f, 0.f);
    int ph0 = 0, ph1 = 0;

    for (int t = 0; t < TSTEPS; t++) {
        int cur = t & 1, nxt = cur ^ 1;

        if (t > 0) {
            uint32_t mb = cur ? mb1 : mb0;
            int ph = cur ? ph1 : ph0;
            // spin on try_wait (acquire): h(t) fully arrived in hsm[cur]
            asm volatile(
                "{\n\t.reg .pred P;\n\t"
                "LW_%=:\n\t"
                "mbarrier.try_wait.parity.acquire.cta.shared::cta.b64 P, [%0], %1, 0x989680;\n\t"
                "@P bra.uni LD_%=;\n\t"
                "bra.uni LW_%=;\n\t"
                "LD_%=:\n\t}"
                :: "r"(mb), "r"(ph) : "memory");
            if (cur) ph1 ^= 1; else ph0 ^= 1;
            if (tid == 0) {  // re-arm this barrier for step t+2
                asm volatile("mbarrier.arrive.expect_tx.shared.b64 _, [%0], %1;"
                             :: "r"(mb), "r"(HX_BYTES) : "memory");
            }
        }

        // prefetch x_gates for the elementwise phase (hidden under GEMM)
        float xg0 = 0.f, xg1 = 0.f, xg2 = 0.f, xg3 = 0.f;
        if (tid < 128) {
            const float* xp = g_xg + ((size_t)t * NBATCH + b0 + eb) * G4SZ + ecol;
            xg0 = xp[0]; xg1 = xp[256]; xg2 = xp[512]; xg3 = xp[768];
        }

        // ---- recurrent GEMM partials: 4 batches, K-quarter qk ----
        float gsum[4];
#pragma unroll
        for (int b = 0; b < 4; b++) {
            const ulonglong2* hp =
                (const ulonglong2*)(hsm + cur * 1024 + b * 256 + qk * 64);
            unsigned long long a = z, c = z;
#pragma unroll
            for (int i = 0; i < 16; i++) {
                ulonglong2 hv = hp[i];
                a = fma2(w2[2 * i + 0], hv.x, a);
                c = fma2(w2[2 * i + 1], hv.y, c);
            }
            float2 p = unpack2(add2(a, c));
            gsum[b] = p.x + p.y;
        }
        *(float4*)(red + (qk * 128 + lr) * 4) =
            make_float4(gsum[0], gsum[1], gsum[2], gsum[3]);
        __syncthreads();

        // ---- elementwise LSTM cell + async h distribution ----
        if (tid < 128) {
            float gs[4];
#pragma unroll
            for (int g = 0; g < 4; g++) {
                int row = g * 32 + eco;
                gs[g] = red[(0 * 128 + row) * 4 + eb]
                      + red[(1 * 128 + row) * 4 + eb]
                      + red[(2 * 128 + row) * 4 + eb]
                      + red[(3 * 128 + row) * 4 + eb];
            }
            float iv = sigf(gs[0] + xg0);
            float fv = sigf(gs[1] + xg1);
            float gv = tanhfastf(gs[2] + xg2);
            float ov = sigf(gs[3] + xg3);
            creg = fv * creg + iv * gv;
            float hn = ov * tanhfastf(creg);

            if (t < TSTEPS - 1) {
                // fire-and-forget h to all 8 cluster CTAs (incl. self)
                uint32_t lh = (uint32_t)__cvta_generic_to_shared(
                    hsm + nxt * 1024 + eb * 256 + ecol);
                uint32_t lm = nxt ? mb1 : mb0;
                uint32_t hb = __float_as_uint(hn);
#pragma unroll
                for (int p = 0; p < 8; p++) {
                    uint32_t ra, rm;
                    asm volatile("mapa.shared::cluster.u32 %0, %1, %2;"
                                 : "=r"(ra) : "r"(lh), "r"(p));
                    asm volatile("mapa.shared::cluster.u32 %0, %1, %2;"
                                 : "=r"(rm) : "r"(lm), "r"(p));
                    asm volatile(
                        "st.async.shared::cluster.mbarrier::complete_tx::bytes.b32 [%0], %1, [%2];"
                        :: "r"(ra), "r"(hb), "r"(rm) : "memory");
                }
            }
            out[((size_t)t * NBATCH + b0 + eb) * HSZ + ecol] = hn;
            if (write_tail && t == TSTEPS - 1) {
                out[OUT_HT + (size_t)(b0 + eb) * HSZ + ecol] = hn;
                out[OUT_CT + (size_t)(b0 + eb) * HSZ + ecol] = creg;
            }
        }
        // no cluster barrier: next iteration's mbarrier wait is the sync
    }
}

// ============================================================
extern "C" void kernel_launch(void* const* d_in, const int* in_sizes, int n_in,
                              void* d_out, int out_size) {
    const float* input = (const float*)d_in[0];
    const float* h0    = (const float*)d_in[1];
    const float* c0    = (const float*)d_in[2];
    const float* W_ih  = (const float*)d_in[3];
    const float* W_hh  = (const float*)d_in[4];
    const float* b_ih  = (const float*)d_in[5];
    const float* b_hh  = (const float*)d_in[6];
    float* out = (float*)d_out;

    int write_tail = (out_size >= (int)(OUT_CT + (size_t)NBATCH * HSZ)) ? 1 : 0;

    dim3 gA((TSTEPS * NBATCH) / BM, G4SZ / BN);
    xg_gemm<<<gA, 256>>>(input, W_ih, b_ih, b_hh);

    lstm_rec<<<128, 512>>>(h0, c0, W_hh, out, write_tail);
}

// round 8
// speedup vs baseline: 1.9913x; 1.0684x over previous
#include <cuda_runtime.h>
#include <cstdint>

#define TSTEPS 2048
#define NBATCH 64
#define ISZ 256
#define HSZ 256
#define G4SZ 1024

// 512 MB scratch for x_gates = input @ W_ih^T + b_ih + b_hh  (T,B,4H)
__device__ float g_xg[(size_t)TSTEPS * NBATCH * G4SZ];

// ---------- packed f32x2 helpers ----------
__device__ __forceinline__ unsigned long long pack2(float x, float y) {
    unsigned long long r;
    asm("mov.b64 %0, {%1, %2};" : "=l"(r) : "f"(x), "f"(y));
    return r;
}
__device__ __forceinline__ unsigned long long fma2(unsigned long long a,
                                                   unsigned long long b,
                                                   unsigned long long c) {
    unsigned long long d;
    asm("fma.rn.f32x2 %0, %1, %2, %3;" : "=l"(d) : "l"(a), "l"(b), "l"(c));
    return d;
}
__device__ __forceinline__ unsigned long long add2(unsigned long long a,
                                                   unsigned long long b) {
    unsigned long long d;
    asm("add.rn.f32x2 %0, %1, %2;" : "=l"(d) : "l"(a), "l"(b));
    return d;
}
__device__ __forceinline__ float2 unpack2(unsigned long long v) {
    float2 r;
    asm("mov.b64 {%0, %1}, %2;" : "=f"(r.x), "=f"(r.y) : "l"(v));
    return r;
}

__device__ __forceinline__ float sigf(float x) {
    return __fdividef(1.f, 1.f + __expf(-x));
}
__device__ __forceinline__ float tanhfastf(float x) {
    return 2.f * __fdividef(1.f, 1.f + __expf(-2.f * x)) - 1.f;
}

// ============================================================
// Kernel A: x_gates GEMM.  C[M=131072, N=1024] = A[M,256] @ W[N,256]^T + bias
// ============================================================
#define BM 128
#define BN 64
#define BK 16
#define ASTR 132
#define BSTR 68

__global__ __launch_bounds__(256) void xg_gemm(
    const float* __restrict__ A, const float* __restrict__ W,
    const float* __restrict__ b1, const float* __restrict__ b2)
{
    __shared__ float As[BK * ASTR];  // [k][m]
    __shared__ float Bs[BK * BSTR];  // [k][n]
    int tid = threadIdx.x;
    int tx = tid & 15, ty = tid >> 4;
    size_t mBase = (size_t)blockIdx.x * BM;
    int nBase = blockIdx.y * BN;

    unsigned long long z = pack2(0.f, 0.f);
    unsigned long long acc[8][2];
#pragma unroll
    for (int i = 0; i < 8; i++) { acc[i][0] = z; acc[i][1] = z; }

    for (int kt = 0; kt < ISZ; kt += BK) {
#pragma unroll
        for (int it = tid; it < (BM * BK / 4); it += 256) {
            int m = it >> 2, kq = it & 3;
            float4 v = *(const float4*)(A + (mBase + m) * ISZ + kt + kq * 4);
            As[(kq * 4 + 0) * ASTR + m] = v.x;
            As[(kq * 4 + 1) * ASTR + m] = v.y;
            As[(kq * 4 + 2) * ASTR + m] = v.z;
            As[(kq * 4 + 3) * ASTR + m] = v.w;
        }
        {
            int n = tid >> 2, kq = tid & 3;
            float4 v = *(const float4*)(W + (size_t)(nBase + n) * ISZ + kt + kq * 4);
            Bs[(kq * 4 + 0) * BSTR + n] = v.x;
            Bs[(kq * 4 + 1) * BSTR + n] = v.y;
            Bs[(kq * 4 + 2) * BSTR + n] = v.z;
            Bs[(kq * 4 + 3) * BSTR + n] = v.w;
        }
        __syncthreads();
#pragma unroll
        for (int kk = 0; kk < BK; kk++) {
            float4 a0 = *(const float4*)(As + kk * ASTR + ty * 8);
            float4 a1 = *(const float4*)(As + kk * ASTR + ty * 8 + 4);
            float4 bv = *(const float4*)(Bs + kk * BSTR + tx * 4);
            unsigned long long bp0 = pack2(bv.x, bv.y);
            unsigned long long bp1 = pack2(bv.z, bv.w);
            float am[8] = {a0.x, a0.y, a0.z, a0.w, a1.x, a1.y, a1.z, a1.w};
#pragma unroll
            for (int i = 0; i < 8; i++) {
                unsigned long long ap = pack2(am[i], am[i]);
                acc[i][0] = fma2(ap, bp0, acc[i][0]);
                acc[i][1] = fma2(ap, bp1, acc[i][1]);
            }
        }
        __syncthreads();
    }
    int n0 = nBase + tx * 4;
    float bx = b1[n0 + 0] + b2[n0 + 0];
    float by = b1[n0 + 1] + b2[n0 + 1];
    float bz = b1[n0 + 2] + b2[n0 + 2];
    float bw = b1[n0 + 3] + b2[n0 + 3];
#pragma unroll
    for (int i = 0; i < 8; i++) {
        float2 p0 = unpack2(acc[i][0]);
        float2 p1 = unpack2(acc[i][1]);
        float4 o = make_float4(p0.x + bx, p0.y + by, p1.x + bz, p1.y + bw);
        *(float4*)(g_xg + (mBase + ty * 8 + i) * G4SZ + n0) = o;
    }
}

// ============================================================
// Kernel B: recurrence. 16 groups x cluster of 8 CTAs, 512 thr/CTA.
// W_hh in registers. h exchange per step: st.async.v4.b32 (16B) messages
// from 32 sender threads -> 256 messages/step at the receiver (vs 1024
// scalar in the round-3 baseline). st.async sources REGISTERS, so the
// local staging buffer has no in-flight-read hazard; its t->t+1 reuse is
// ordered by the full-CTA __syncthreads between steps.
// h layout: hsm[buf][src_rank_block][batch][32 cols].
// ============================================================
#define OUT_HT ((size_t)TSTEPS * NBATCH * HSZ)
#define OUT_CT (OUT_HT + (size_t)NBATCH * HSZ)
#define HX_BYTES 4096   // 8 CTAs * 512B received per step

__global__ void __cluster_dims__(8, 1, 1) __launch_bounds__(512, 1) lstm_rec(
    const float* __restrict__ h0, const float* __restrict__ c0,
    const float* __restrict__ Whh, float* __restrict__ out, int write_tail)
{
    __shared__ __align__(16) float hsm[2 * 1024];    // [buf][blk][b][co] 8KB
    __shared__ __align__(16) float red[4 * 4 * 128]; // [qk][b][row]      8KB
    __shared__ __align__(16) float stage[128];       // [b][co] outgoing 512B
    __shared__ __align__(8) unsigned long long mbars[2];

    int tid = threadIdx.x;
    unsigned crank;
    asm("mov.u32 %0, %%cluster_ctarank;" : "=r"(crank));
    int b0 = (blockIdx.x >> 3) * 4;

    int qk = tid >> 7, lr = tid & 127;
    int gr = (lr >> 5) * 256 + (int)crank * 32 + (lr & 31);  // global gate row

    uint32_t mb0 = (uint32_t)__cvta_generic_to_shared(&mbars[0]);
    uint32_t mb1 = (uint32_t)__cvta_generic_to_shared(&mbars[1]);

    // ---- W_hh slice -> registers, pre-paired for f32x2 ----
    unsigned long long w2[32];
    {
        const float* wp = Whh + (size_t)gr * HSZ + qk * 64;
#pragma unroll
        for (int i = 0; i < 16; i++) {
            float4 v = *(const float4*)(wp + i * 4);
            w2[i * 2 + 0] = pack2(v.x, v.y);
            w2[i * 2 + 1] = pack2(v.z, v.w);
        }
    }
    // ---- init h buffer 0: hsm[blk*128 + b*32 + co] = h0[b0+b][blk*32+co] ----
    for (int it = tid; it < 1024; it += 512) {
        int blk = it >> 7, b = (it >> 5) & 3, co = it & 31;
        hsm[it] = h0[(size_t)(b0 + b) * HSZ + blk * 32 + co];
    }
    // ---- elementwise state (tid<128): (batch eb, col eco) ----
    int eb = tid >> 5, eco = tid & 31;
    int ecol = (int)crank * 32 + eco;
    float creg = 0.f;
    if (tid < 128) creg = c0[(size_t)(b0 + eb) * HSZ + ecol];

    // ---- mbarrier init + arm ----
    if (tid == 0) {
        asm volatile("mbarrier.init.shared.b64 [%0], 1;" :: "r"(mb0) : "memory");
        asm volatile("mbarrier.init.shared.b64 [%0], 1;" :: "r"(mb1) : "memory");
    }
    __syncthreads();
    if (tid == 0) {
        asm volatile("mbarrier.arrive.expect_tx.shared.b64 _, [%0], %1;"
                     :: "r"(mb0), "r"(HX_BYTES) : "memory");
        asm volatile("mbarrier.arrive.expect_tx.shared.b64 _, [%0], %1;"
                     :: "r"(mb1), "r"(HX_BYTES) : "memory");
    }
    __syncthreads();
    // all cluster CTAs' barriers live before any peer st.async
    asm volatile("barrier.cluster.arrive.aligned;" ::: "memory");
    asm volatile("barrier.cluster.wait.aligned;" ::: "memory");

    unsigned long long z = pack2(0.f, 0.f);
    int ph0 = 0, ph1 = 0;

    for (int t = 0; t < TSTEPS; t++) {
        int cur = t & 1, nxt = cur ^ 1;

        // x_gates prefetch BEFORE the wait (hides L2/DRAM latency)
        float xg0 = 0.f, xg1 = 0.f, xg2 = 0.f, xg3 = 0.f;
        if (tid < 128) {
            const float* xp = g_xg + ((size_t)t * NBATCH + b0 + eb) * G4SZ + ecol;
            xg0 = xp[0]; xg1 = xp[256]; xg2 = xp[512]; xg3 = xp[768];
        }

        if (t > 0) {
            uint32_t mb = cur ? mb1 : mb0;
            int ph = cur ? ph1 : ph0;
            asm volatile(
                "{\n\t.reg .pred P;\n\t"
                "LW_%=:\n\t"
                "mbarrier.try_wait.parity.acquire.cta.shared::cta.b64 P, [%0], %1, 0x989680;\n\t"
                "@P bra.uni LD_%=;\n\t"
                "bra.uni LW_%=;\n\t"
                "LD_%=:\n\t}"
                :: "r"(mb), "r"(ph) : "memory");
            if (cur) ph1 ^= 1; else ph0 ^= 1;
            if (tid == 0) {  // re-arm for step t+2
                asm volatile("mbarrier.arrive.expect_tx.shared.b64 _, [%0], %1;"
                             :: "r"(mb), "r"(HX_BYTES) : "memory");
            }
        }

        // ---- recurrent GEMM partials: 4 batches, K-quarter qk ----
        float gsum[4];
#pragma unroll
        for (int b = 0; b < 4; b++) {
            unsigned long long a = z, c = z;
#pragma unroll
            for (int kb = 0; kb < 2; kb++) {
                const ulonglong2* hp = (const ulonglong2*)(
                    hsm + cur * 1024 + (2 * qk + kb) * 128 + b * 32);
#pragma unroll
                for (int i = 0; i < 8; i++) {
                    ulonglong2 hv = hp[i];
                    a = fma2(w2[kb * 16 + 2 * i + 0], hv.x, a);
                    c = fma2(w2[kb * 16 + 2 * i + 1], hv.y, c);
                }
            }
            float2 p = unpack2(add2(a, c));
            gsum[b] = p.x + p.y;
        }
        // conflict-free partial store: red[qk][b][lr]
#pragma unroll
        for (int b = 0; b < 4; b++)
            red[(qk * 4 + b) * 128 + lr] = gsum[b];
        __syncthreads();

        // ---- elementwise LSTM cell + v4 st.async h distribution ----
        if (tid < 128) {
            float gs[4];
#pragma unroll
            for (int g = 0; g < 4; g++) {
                int row = g * 32 + eco;
                gs[g] = red[(0 * 4 + eb) * 128 + row]
                      + red[(1 * 4 + eb) * 128 + row]
                      + red[(2 * 4 + eb) * 128 + row]
                      + red[(3 * 4 + eb) * 128 + row];
            }
            float iv = sigf(gs[0] + xg0);
            float fv = sigf(gs[1] + xg1);
            float gv = tanhfastf(gs[2] + xg2);
            float ov = sigf(gs[3] + xg3);
            creg = fv * creg + iv * gv;
            float hn = ov * tanhfastf(creg);

            if (t < TSTEPS - 1) {
                stage[eb * 32 + eco] = hn;
                asm volatile("bar.sync 1, 128;" ::: "memory");
                if (tid < 32) {
                    // thread tid sends 16B chunk tid: floats [tid*4, tid*4+4)
                    uint4 v = *(const uint4*)(stage + tid * 4);
                    uint32_t ldst = (uint32_t)__cvta_generic_to_shared(
                        hsm + nxt * 1024 + (int)crank * 128 + tid * 4);
                    uint32_t lmb = nxt ? mb1 : mb0;
#pragma unroll
                    for (int p = 0; p < 8; p++) {
                        uint32_t rdst, rmb;
                        asm volatile("mapa.shared::cluster.u32 %0, %1, %2;"
                                     : "=r"(rdst) : "r"(ldst), "r"(p));
                        asm volatile("mapa.shared::cluster.u32 %0, %1, %2;"
                                     : "=r"(rmb) : "r"(lmb), "r"(p));
                        asm volatile(
                            "st.async.shared::cluster.mbarrier::complete_tx::bytes.v4.b32 "
                            "[%0], {%1, %2, %3, %4}, [%5];"
                            :: "r"(rdst), "r"(v.x), "r"(v.y), "r"(v.z), "r"(v.w),
                               "r"(rmb) : "memory");
                    }
                }
            }
            out[((size_t)t * NBATCH + b0 + eb) * HSZ + ecol] = hn;
            if (write_tail && t == TSTEPS - 1) {
                out[OUT_HT + (size_t)(b0 + eb) * HSZ + ecol] = hn;
                out[OUT_CT + (size_t)(b0 + eb) * HSZ + ecol] = creg;
            }
        }
        // no cluster barrier: next iteration's mbarrier wait is the sync
    }
}

// ============================================================
extern "C" void kernel_launch(void* const* d_in, const int* in_sizes, int n_in,
                              void* d_out, int out_size) {
    const float* input = (const float*)d_in[0];
    const float* h0    = (const float*)d_in[1];
    const float* c0    = (const float*)d_in[2];
    const float* W_ih  = (const float*)d_in[3];
    const float* W_hh  = (const float*)d_in[4];
    const float* b_ih  = (const float*)d_in[5];
    const float* b_hh  = (const float*)d_in[6];
    float* out = (float*)d_out;

    int write_tail = (out_size >= (int)(OUT_CT + (size_t)NBATCH * HSZ)) ? 1 : 0;

    dim3 gA((TSTEPS * NBATCH) / BM, G4SZ / BN);
    xg_gemm<<<gA, 256>>>(input, W_ih, b_ih, b_hh);

    lstm_rec<<<128, 512>>>(h0, c0, W_hh, out, write_tail);
}

// round 9
// speedup vs baseline: 2.0877x; 1.0484x over previous
#include <cuda_runtime.h>
#include <cstdint>

#define TSTEPS 2048
#define NBATCH 64
#define ISZ 256
#define HSZ 256
#define G4SZ 1024

// 512 MB scratch for x_gates = input @ W_ih^T + b_ih + b_hh  (T,B,4H)
__device__ float g_xg[(size_t)TSTEPS * NBATCH * G4SZ];

// ---------- packed f32x2 helpers ----------
__device__ __forceinline__ unsigned long long pack2(float x, float y) {
    unsigned long long r;
    asm("mov.b64 %0, {%1, %2};" : "=l"(r) : "f"(x), "f"(y));
    return r;
}
__device__ __forceinline__ unsigned long long fma2(unsigned long long a,
                                                   unsigned long long b,
                                                   unsigned long long c) {
    unsigned long long d;
    asm("fma.rn.f32x2 %0, %1, %2, %3;" : "=l"(d) : "l"(a), "l"(b), "l"(c));
    return d;
}
__device__ __forceinline__ unsigned long long add2(unsigned long long a,
                                                   unsigned long long b) {
    unsigned long long d;
    asm("add.rn.f32x2 %0, %1, %2;" : "=l"(d) : "l"(a), "l"(b));
    return d;
}
__device__ __forceinline__ float2 unpack2(unsigned long long v) {
    float2 r;
    asm("mov.b64 {%0, %1}, %2;" : "=f"(r.x), "=f"(r.y) : "l"(v));
    return r;
}

__device__ __forceinline__ float sigf(float x) {
    return __fdividef(1.f, 1.f + __expf(-x));
}
__device__ __forceinline__ float tanhfastf(float x) {
    return 2.f * __fdividef(1.f, 1.f + __expf(-2.f * x)) - 1.f;
}

// ============================================================
// Kernel A: x_gates GEMM.  C[M=131072, N=1024] = A[M,256] @ W[N,256]^T + bias
// ============================================================
#define BM 128
#define BN 64
#define BK 16
#define ASTR 132
#define BSTR 68

__global__ __launch_bounds__(256) void xg_gemm(
    const float* __restrict__ A, const float* __restrict__ W,
    const float* __restrict__ b1, const float* __restrict__ b2)
{
    __shared__ float As[BK * ASTR];  // [k][m]
    __shared__ float Bs[BK * BSTR];  // [k][n]
    int tid = threadIdx.x;
    int tx = tid & 15, ty = tid >> 4;
    size_t mBase = (size_t)blockIdx.x * BM;
    int nBase = blockIdx.y * BN;

    unsigned long long z = pack2(0.f, 0.f);
    unsigned long long acc[8][2];
#pragma unroll
    for (int i = 0; i < 8; i++) { acc[i][0] = z; acc[i][1] = z; }

    for (int kt = 0; kt < ISZ; kt += BK) {
#pragma unroll
        for (int it = tid; it < (BM * BK / 4); it += 256) {
            int m = it >> 2, kq = it & 3;
            float4 v = *(const float4*)(A + (mBase + m) * ISZ + kt + kq * 4);
            As[(kq * 4 + 0) * ASTR + m] = v.x;
            As[(kq * 4 + 1) * ASTR + m] = v.y;
            As[(kq * 4 + 2) * ASTR + m] = v.z;
            As[(kq * 4 + 3) * ASTR + m] = v.w;
        }
        {
            int n = tid >> 2, kq = tid & 3;
            float4 v = *(const float4*)(W + (size_t)(nBase + n) * ISZ + kt + kq * 4);
            Bs[(kq * 4 + 0) * BSTR + n] = v.x;
            Bs[(kq * 4 + 1) * BSTR + n] = v.y;
            Bs[(kq * 4 + 2) * BSTR + n] = v.z;
            Bs[(kq * 4 + 3) * BSTR + n] = v.w;
        }
        __syncthreads();
#pragma unroll
        for (int kk = 0; kk < BK; kk++) {
            float4 a0 = *(const float4*)(As + kk * ASTR + ty * 8);
            float4 a1 = *(const float4*)(As + kk * ASTR + ty * 8 + 4);
            float4 bv = *(const float4*)(Bs + kk * BSTR + tx * 4);
            unsigned long long bp0 = pack2(bv.x, bv.y);
            unsigned long long bp1 = pack2(bv.z, bv.w);
            float am[8] = {a0.x, a0.y, a0.z, a0.w, a1.x, a1.y, a1.z, a1.w};
#pragma unroll
            for (int i = 0; i < 8; i++) {
                unsigned long long ap = pack2(am[i], am[i]);
                acc[i][0] = fma2(ap, bp0, acc[i][0]);
                acc[i][1] = fma2(ap, bp1, acc[i][1]);
            }
        }
        __syncthreads();
    }
    int n0 = nBase + tx * 4;
    float bx = b1[n0 + 0] + b2[n0 + 0];
    float by = b1[n0 + 1] + b2[n0 + 1];
    float bz = b1[n0 + 2] + b2[n0 + 2];
    float bw = b1[n0 + 3] + b2[n0 + 3];
#pragma unroll
    for (int i = 0; i < 8; i++) {
        float2 p0 = unpack2(acc[i][0]);
        float2 p1 = unpack2(acc[i][1]);
        float4 o = make_float4(p0.x + bx, p0.y + by, p1.x + bz, p1.y + bw);
        *(float4*)(g_xg + (mBase + ty * 8 + i) * G4SZ + n0) = o;
    }
}

// ============================================================
// Kernel B: recurrence. 8 clusters x 8 CTAs, 512 thr/CTA.
// Each cluster owns TWO independent 4-batch groups (A, B), software-
// pipelined inside one loop so group B's compute hides group A's DSMEM
// round trip and vice versa. W_hh registers shared between groups.
// Exchange: st.async.v4.b32 (16B) from 32 sender threads per group.
// h layout per group: hsm[buf][src_rank_block][batch][32 cols].
// ============================================================
#define OUT_HT ((size_t)TSTEPS * NBATCH * HSZ)
#define OUT_CT (OUT_HT + (size_t)NBATCH * HSZ)
#define HX_BYTES 4096   // 8 CTAs * 512B received per step per group

// recurrent GEMM partials for one group: 4 batches, K-quarter qk
__device__ __forceinline__ void rec_gemm(
    const float* __restrict__ hbuf, float* __restrict__ red,
    const unsigned long long* __restrict__ w2, int qk, int lr,
    unsigned long long z)
{
    float gsum[4];
#pragma unroll
    for (int b = 0; b < 4; b++) {
        unsigned long long a = z, c = z;
#pragma unroll
        for (int kb = 0; kb < 2; kb++) {
            const ulonglong2* hp = (const ulonglong2*)(
                hbuf + (2 * qk + kb) * 128 + b * 32);
#pragma unroll
            for (int i = 0; i < 8; i++) {
                ulonglong2 hv = hp[i];
                a = fma2(w2[kb * 16 + 2 * i + 0], hv.x, a);
                c = fma2(w2[kb * 16 + 2 * i + 1], hv.y, c);
            }
        }
        float2 p = unpack2(add2(a, c));
        gsum[b] = p.x + p.y;
    }
#pragma unroll
    for (int b = 0; b < 4; b++)
        red[(qk * 4 + b) * 128 + lr] = gsum[b];
}

#define MBAR_WAIT(mb, ph)                                                      \
    asm volatile(                                                              \
        "{\n\t.reg .pred P;\n\t"                                               \
        "LW_%=:\n\t"                                                           \
        "mbarrier.try_wait.parity.acquire.cta.shared::cta.b64 P, [%0], %1, 0x989680;\n\t" \
        "@P bra.uni LD_%=;\n\t"                                                \
        "bra.uni LW_%=;\n\t"                                                   \
        "LD_%=:\n\t}" :: "r"(mb), "r"(ph) : "memory")

__global__ void __cluster_dims__(8, 1, 1) __launch_bounds__(512, 1) lstm_rec(
    const float* __restrict__ h0, const float* __restrict__ c0,
    const float* __restrict__ Whh, float* __restrict__ out, int write_tail)
{
    __shared__ __align__(16) float hsmA[2 * 1024];   // 8KB
    __shared__ __align__(16) float hsmB[2 * 1024];   // 8KB
    __shared__ __align__(16) float redA[4 * 4 * 128];// 8KB
    __shared__ __align__(16) float redB[4 * 4 * 128];// 8KB
    __shared__ __align__(16) float stageA[128];
    __shared__ __align__(16) float stageB[128];
    __shared__ __align__(8) unsigned long long mbars[4]; // A0 A1 B0 B1

    int tid = threadIdx.x;
    unsigned crank;
    asm("mov.u32 %0, %%cluster_ctarank;" : "=r"(crank));
    int cid = blockIdx.x >> 3;
    int b0A = cid * 8;
    int b0B = b0A + 4;

    int qk = tid >> 7, lr = tid & 127;
    int gr = (lr >> 5) * 256 + (int)crank * 32 + (lr & 31);  // global gate row

    uint32_t mbA0 = (uint32_t)__cvta_generic_to_shared(&mbars[0]);
    uint32_t mbA1 = (uint32_t)__cvta_generic_to_shared(&mbars[1]);
    uint32_t mbB0 = (uint32_t)__cvta_generic_to_shared(&mbars[2]);
    uint32_t mbB1 = (uint32_t)__cvta_generic_to_shared(&mbars[3]);

    // ---- W_hh slice -> registers, pre-paired for f32x2 (shared A/B) ----
    unsigned long long w2[32];
    {
        const float* wp = Whh + (size_t)gr * HSZ + qk * 64;
#pragma unroll
        for (int i = 0; i < 16; i++) {
            float4 v = *(const float4*)(wp + i * 4);
            w2[i * 2 + 0] = pack2(v.x, v.y);
            w2[i * 2 + 1] = pack2(v.z, v.w);
        }
    }
    // ---- init h buffer 0 for both groups ----
    for (int it = tid; it < 1024; it += 512) {
        int blk = it >> 7, b = (it >> 5) & 3, co = it & 31;
        hsmA[it] = h0[(size_t)(b0A + b) * HSZ + blk * 32 + co];
        hsmB[it] = h0[(size_t)(b0B + b) * HSZ + blk * 32 + co];
    }
    // ---- elementwise state (tid<128): (batch eb, col eco) ----
    int eb = tid >> 5, eco = tid & 31;
    int ecol = (int)crank * 32 + eco;
    float cregA = 0.f, cregB = 0.f;
    if (tid < 128) {
        cregA = c0[(size_t)(b0A + eb) * HSZ + ecol];
        cregB = c0[(size_t)(b0B + eb) * HSZ + ecol];
    }

    // ---- mbarrier init + arm ----
    if (tid == 0) {
#pragma unroll
        for (int i = 0; i < 4; i++) {
            uint32_t mb = (uint32_t)__cvta_generic_to_shared(&mbars[i]);
            asm volatile("mbarrier.init.shared.b64 [%0], 1;" :: "r"(mb) : "memory");
        }
    }
    __syncthreads();
    if (tid == 0) {
#pragma unroll
        for (int i = 0; i < 4; i++) {
            uint32_t mb = (uint32_t)__cvta_generic_to_shared(&mbars[i]);
            asm volatile("mbarrier.arrive.expect_tx.shared.b64 _, [%0], %1;"
                         :: "r"(mb), "r"(HX_BYTES) : "memory");
        }
    }
    __syncthreads();
    // all cluster CTAs' barriers live before any peer st.async
    asm volatile("barrier.cluster.arrive.aligned;" ::: "memory");
    asm volatile("barrier.cluster.wait.aligned;" ::: "memory");

    unsigned long long z = pack2(0.f, 0.f);
    int phA0 = 0, phA1 = 0, phB0 = 0, phB1 = 0;

    for (int t = 0; t < TSTEPS; t++) {
        int cur = t & 1, nxt = cur ^ 1;

        // ---------------- group A ----------------
        float xg0 = 0.f, xg1 = 0.f, xg2 = 0.f, xg3 = 0.f;
        if (tid < 128) {
            const float* xp = g_xg + ((size_t)t * NBATCH + b0A + eb) * G4SZ + ecol;
            xg0 = xp[0]; xg1 = xp[256]; xg2 = xp[512]; xg3 = xp[768];
        }
        if (t > 0) {
            uint32_t mb = cur ? mbA1 : mbA0;
            int ph = cur ? phA1 : phA0;
            MBAR_WAIT(mb, ph);
            if (cur) phA1 ^= 1; else phA0 ^= 1;
            if (tid == 0)
                asm volatile("mbarrier.arrive.expect_tx.shared.b64 _, [%0], %1;"
                             :: "r"(mb), "r"(HX_BYTES) : "memory");
        }
        rec_gemm(hsmA + cur * 1024, redA, w2, qk, lr, z);
        __syncthreads();

        float xb0 = 0.f, xb1 = 0.f, xb2 = 0.f, xb3 = 0.f;
        if (tid < 128) {
            // prefetch group-B x_gates early (hidden under EW_A + GEMM_B)
            const float* xq = g_xg + ((size_t)t * NBATCH + b0B + eb) * G4SZ + ecol;
            xb0 = xq[0]; xb1 = xq[256]; xb2 = xq[512]; xb3 = xq[768];

            float gs[4];
#pragma unroll
            for (int g = 0; g < 4; g++) {
                int row = g * 32 + eco;
                gs[g] = redA[(0 * 4 + eb) * 128 + row]
                      + redA[(1 * 4 + eb) * 128 + row]
                      + redA[(2 * 4 + eb) * 128 + row]
                      + redA[(3 * 4 + eb) * 128 + row];
            }
            float iv = sigf(gs[0] + xg0);
            float fv = sigf(gs[1] + xg1);
            float gv = tanhfastf(gs[2] + xg2);
            float ov = sigf(gs[3] + xg3);
            cregA = fv * cregA + iv * gv;
            float hn = ov * tanhfastf(cregA);

            out[((size_t)t * NBATCH + b0A + eb) * HSZ + ecol] = hn;
            if (t < TSTEPS - 1) {
                stageA[eb * 32 + eco] = hn;
                asm volatile("bar.sync 1, 128;" ::: "memory");
                if (tid < 32) {
                    uint4 v = *(const uint4*)(stageA + tid * 4);
                    uint32_t ldst = (uint32_t)__cvta_generic_to_shared(
                        hsmA + nxt * 1024 + (int)crank * 128 + tid * 4);
                    uint32_t lmb = nxt ? mbA1 : mbA0;
#pragma unroll
                    for (int p = 0; p < 8; p++) {
                        uint32_t rdst, rmb;
                        asm volatile("mapa.shared::cluster.u32 %0, %1, %2;"
                                     : "=r"(rdst) : "r"(ldst), "r"(p));
                        asm volatile("mapa.shared::cluster.u32 %0, %1, %2;"
                                     : "=r"(rmb) : "r"(lmb), "r"(p));
                        asm volatile(
                            "st.async.shared::cluster.mbarrier::complete_tx::bytes.v4.b32 "
                            "[%0], {%1, %2, %3, %4}, [%5];"
                            :: "r"(rdst), "r"(v.x), "r"(v.y), "r"(v.z), "r"(v.w),
                               "r"(rmb) : "memory");
                    }
                }
            } else if (write_tail) {
                out[OUT_HT + (size_t)(b0A + eb) * HSZ + ecol] = hn;
                out[OUT_CT + (size_t)(b0A + eb) * HSZ + ecol] = cregA;
            }
        }

        // ---------------- group B ----------------
        if (t > 0) {
            uint32_t mb = cur ? mbB1 : mbB0;
            int ph = cur ? phB1 : phB0;
            MBAR_WAIT(mb, ph);
            if (cur) phB1 ^= 1; else phB0 ^= 1;
            if (tid == 0)
                asm volatile("mbarrier.arrive.expect_tx.shared.b64 _, [%0], %1;"
                             :: "r"(mb), "r"(HX_BYTES) : "memory");
        }
        rec_gemm(hsmB + cur * 1024, redB, w2, qk, lr, z);
        __syncthreads();

        if (tid < 128) {
            float gs[4];
#pragma unroll
            for (int g = 0; g < 4; g++) {
                int row = g * 32 + eco;
                gs[g] = redB[(0 * 4 + eb) * 128 + row]
                      + redB[(1 * 4 + eb) * 128 + row]
                      + redB[(2 * 4 + eb) * 128 + row]
                      + redB[(3 * 4 + eb) * 128 + row];
            }
            float iv = sigf(gs[0] + xb0);
            float fv = sigf(gs[1] + xb1);
            float gv = tanhfastf(gs[2] + xb2);
            float ov = sigf(gs[3] + xb3);
            cregB = fv * cregB + iv * gv;
            float hn = ov * tanhfastf(cregB);

            out[((size_t)t * NBATCH + b0B + eb) * HSZ + ecol] = hn;
            if (t < TSTEPS - 1) {
                stageB[eb * 32 + eco] = hn;
                asm volatile("bar.sync 1, 128;" ::: "memory");
                if (tid < 32) {
                    uint4 v = *(const uint4*)(stageB + tid * 4);
                    uint32_t ldst = (uint32_t)__cvta_generic_to_shared(
                        hsmB + nxt * 1024 + (int)crank * 128 + tid * 4);
                    uint32_t lmb = nxt ? mbB1 : mbB0;
#pragma unroll
                    for (int p = 0; p < 8; p++) {
                        uint32_t rdst, rmb;
                        asm volatile("mapa.shared::cluster.u32 %0, %1, %2;"
                                     : "=r"(rdst) : "r"(ldst), "r"(p));
                        asm volatile("mapa.shared::cluster.u32 %0, %1, %2;"
                                     : "=r"(rmb) : "r"(lmb), "r"(p));
                        asm volatile(
                            "st.async.shared::cluster.mbarrier::complete_tx::bytes.v4.b32 "
                            "[%0], {%1, %2, %3, %4}, [%5];"
                            :: "r"(rdst), "r"(v.x), "r"(v.y), "r"(v.z), "r"(v.w),
                               "r"(rmb) : "memory");
                    }
                }
            } else if (write_tail) {
                out[OUT_HT + (size_t)(b0B + eb) * HSZ + ecol] = hn;
                out[OUT_CT + (size_t)(b0B + eb) * HSZ + ecol] = cregB;
            }
        }
    }
}

// ============================================================
extern "C" void kernel_launch(void* const* d_in, const int* in_sizes, int n_in,
                              void* d_out, int out_size) {
    const float* input = (const float*)d_in[0];
    const float* h0    = (const float*)d_in[1];
    const float* c0    = (const float*)d_in[2];
    const float* W_ih  = (const float*)d_in[3];
    const float* W_hh  = (const float*)d_in[4];
    const float* b_ih  = (const float*)d_in[5];
    const float* b_hh  = (const float*)d_in[6];
    float* out = (float*)d_out;

    int write_tail = (out_size >= (int)(OUT_CT + (size_t)NBATCH * HSZ)) ? 1 : 0;

    dim3 gA((TSTEPS * NBATCH) / BM, G4SZ / BN);
    xg_gemm<<<gA, 256>>>(input, W_ih, b_ih, b_hh);

    lstm_rec<<<64, 512>>>(h0, c0, W_hh, out, write_tail);
}